// round 7
// baseline (speedup 1.0000x reference)
#include <cuda_runtime.h>
#include <cuda_bf16.h>
#include <cstdint>
#include <cmath>

#define NROWS 8192
#define XROWS 16384
#define DIM   64
#define BT    128                 // tile dim
#define NT    (XROWS / BT)        // 128 tiles per side
#define RPADB 80                  // padded smem row stride in bytes (64 data + 16 pad)

#define SCALE_L2E 28.853900817779268f          // 20 * log2(e)
#define CMUL (28.853900817779268f / 16129.0f)  // 20*log2(e)/127^2

// ---------------- device scratch ----------------
__device__ __align__(16) signed char g_Xq[XROWS * DIM];  // round(127 * normalized)
__device__ float g_part[XROWS];
__device__ float g_pos[NROWS];

static __device__ __forceinline__ uint32_t smem_u32(const void* p) {
    uint32_t a;
    asm("{ .reg .u64 t; cvta.to.shared.u64 t, %1; cvt.u32.u64 %0, t; }" : "=r"(a) : "l"(p));
    return a;
}
static __device__ __forceinline__ float ex2f(float x) {
    float y; asm("ex2.approx.ftz.f32 %0, %1;" : "=f"(y) : "f"(x)); return y;
}

// ---------------- kernel 1: normalize + s8 quantize + exact pos logit + zeroing ----------------
__global__ void prep_kernel(const float* __restrict__ A, const float* __restrict__ P,
                            float* __restrict__ out) {
    int row  = blockIdx.x * 8 + (threadIdx.x >> 5);
    int lane = threadIdx.x & 31;
    float a0 = A[(size_t)row * DIM + lane], a1 = A[(size_t)row * DIM + lane + 32];
    float p0 = P[(size_t)row * DIM + lane], p1 = P[(size_t)row * DIM + lane + 32];
    float sa = a0 * a0 + a1 * a1;
    float sp = p0 * p0 + p1 * p1;
    float d  = a0 * p0 + a1 * p1;
    #pragma unroll
    for (int o = 16; o; o >>= 1) {
        sa += __shfl_xor_sync(0xffffffffu, sa, o);
        sp += __shfl_xor_sync(0xffffffffu, sp, o);
        d  += __shfl_xor_sync(0xffffffffu, d,  o);
    }
    float ra = rsqrtf(fmaxf(sa, 1e-24f));
    float rp = rsqrtf(fmaxf(sp, 1e-24f));
    size_t ia = (size_t)row * DIM, ip = (size_t)(row + NROWS) * DIM;
    g_Xq[ia + lane]      = (signed char)__float2int_rn(127.0f * a0 * ra);
    g_Xq[ia + lane + 32] = (signed char)__float2int_rn(127.0f * a1 * ra);
    g_Xq[ip + lane]      = (signed char)__float2int_rn(127.0f * p0 * rp);
    g_Xq[ip + lane + 32] = (signed char)__float2int_rn(127.0f * p1 * rp);
    if (lane == 0) {
        g_pos[row] = 20.0f * d / fmaxf(sqrtf(sa) * sqrtf(sp), 1e-6f);
        g_part[row] = 0.0f;
        g_part[row + NROWS] = 0.0f;
    }
    if (blockIdx.x == 0 && threadIdx.x == 0) out[0] = 0.0f;
}

// ---------------- kernel 2: full-grid s8 tile GEMM (IMMA k32) + exp + ROW sums ----------------
// Tile (bi,bj) of exp(20*cos(X,X)); s32 dot exact; scale 20*log2e/127^2 folded into ex2 arg.
// Row sums only; global diagonal element skipped (replaces -2*e^{1/T}).
__global__ void __launch_bounds__(256, 2) mma_kernel() {
    __shared__ signed char Ls[BT][RPADB];
    __shared__ signed char Rs[BT][RPADB];

    int bi = blockIdx.y, bj = blockIdx.x;
    int tid = threadIdx.x, wid = tid >> 5, lane = tid & 31;

    // cooperative loads: 128 rows x 64 bytes = 512 uint4 per tile
    const uint4* Lg = (const uint4*)(g_Xq + (size_t)bi * BT * DIM);
    const uint4* Rg = (const uint4*)(g_Xq + (size_t)bj * BT * DIM);
    #pragma unroll
    for (int it = 0; it < 2; ++it) {
        int f = tid + it * 256;        // f in [0,512): row = f/4, 16B chunk = f%4
        int r = f >> 2, kc = (f & 3) * 16;
        *(uint4*)&Ls[r][kc] = Lg[f];
        *(uint4*)&Rs[r][kc] = Rg[f];
    }
    __syncthreads();

    bool diag = (bi == bj);
    int grow0 = bi * BT, gcol0 = bj * BT;
    int gid = lane >> 2, tig = lane & 3;

    // A fragments: warp's 16-row strip, K=64 s8 = 2 kc chunks of k32
    uint32_t a[2][4];
    {
        int r  = wid * 16 + (lane & 15);
        int kh = (lane >> 4) * 16;     // 16-byte k-half within k32 chunk
        #pragma unroll
        for (int kc = 0; kc < 2; ++kc) {
            uint32_t addr = smem_u32(&Ls[r][kc * 32 + kh]);
            asm volatile("ldmatrix.sync.aligned.m8n8.x4.shared.b16 {%0,%1,%2,%3}, [%4];"
                         : "=r"(a[kc][0]), "=r"(a[kc][1]), "=r"(a[kc][2]), "=r"(a[kc][3])
                         : "r"(addr));
        }
    }

    int myrow0 = grow0 + wid * 16 + gid;
    int myrow1 = myrow0 + 8;
    float row0s = 0.0f, row1s = 0.0f;

    // B x4-ldmatrix lane mapping: lanes 0-7 -> (u0,h0), 8-15 -> (u0,h1),
    //                             16-23 -> (u1,h0), 24-31 -> (u1,h1)
    int b_u = (lane >> 4) & 1;
    int b_h = (lane >> 3) & 1;
    int b_r = lane & 7;

    #pragma unroll
    for (int n2 = 0; n2 < 8; ++n2) {
        uint32_t b[2][2][2];   // [kc][u][half]
        #pragma unroll
        for (int kc = 0; kc < 2; ++kc) {
            uint32_t addr = smem_u32(&Rs[n2 * 16 + b_u * 8 + b_r][kc * 32 + b_h * 16]);
            asm volatile("ldmatrix.sync.aligned.m8n8.x4.shared.b16 {%0,%1,%2,%3}, [%4];"
                         : "=r"(b[kc][0][0]), "=r"(b[kc][0][1]),
                           "=r"(b[kc][1][0]), "=r"(b[kc][1][1])
                         : "r"(addr));
        }
        int c[2][4] = {};
        #pragma unroll
        for (int kc = 0; kc < 2; ++kc) {
            #pragma unroll
            for (int u = 0; u < 2; ++u) {
                asm volatile(
                    "mma.sync.aligned.m16n8k32.row.col.s32.s8.s8.s32 "
                    "{%0,%1,%2,%3}, {%4,%5,%6,%7}, {%8,%9}, {%0,%1,%2,%3};"
                    : "+r"(c[u][0]), "+r"(c[u][1]), "+r"(c[u][2]), "+r"(c[u][3])
                    : "r"(a[kc][0]), "r"(a[kc][1]), "r"(a[kc][2]), "r"(a[kc][3]),
                      "r"(b[kc][u][0]), "r"(b[kc][u][1]));
            }
        }
        #pragma unroll
        for (int u = 0; u < 2; ++u) {
            float e0 = ex2f((float)c[u][0] * CMUL);
            float e1 = ex2f((float)c[u][1] * CMUL);
            float e2 = ex2f((float)c[u][2] * CMUL);
            float e3 = ex2f((float)c[u][3] * CMUL);
            if (diag) {   // zero the single global-diagonal element
                int gc0 = gcol0 + (n2 * 2 + u) * 8 + tig * 2;
                if (gc0     == myrow0) e0 = 0.0f;
                if (gc0 + 1 == myrow0) e1 = 0.0f;
                if (gc0     == myrow1) e2 = 0.0f;
                if (gc0 + 1 == myrow1) e3 = 0.0f;
            }
            row0s += e0 + e1;
            row1s += e2 + e3;
        }
    }

    // reduce over the 4 lanes (tig) sharing each row, then global accumulate
    #pragma unroll
    for (int o = 1; o < 4; o <<= 1) {
        row0s += __shfl_xor_sync(0xffffffffu, row0s, o);
        row1s += __shfl_xor_sync(0xffffffffu, row1s, o);
    }
    if (tig == 0) {
        atomicAdd(&g_part[myrow0], row0s);
        atomicAdd(&g_part[myrow1], row1s);
    }
}

// ---------------- kernel 3: loss reduction straight into d_out ----------------
__global__ void loss_kernel(float* __restrict__ out) {
    __shared__ float wsum[8];
    int i = blockIdx.x * 256 + threadIdx.x;
    float s = __logf(g_part[i] + g_part[i + NROWS]) - g_pos[i];
    #pragma unroll
    for (int o = 16; o; o >>= 1) s += __shfl_xor_sync(0xffffffffu, s, o);
    int wid = threadIdx.x >> 5, lane = threadIdx.x & 31;
    if (lane == 0) wsum[wid] = s;
    __syncthreads();
    if (wid == 0) {
        float v = (lane < 8) ? wsum[lane] : 0.0f;
        #pragma unroll
        for (int o = 4; o; o >>= 1) v += __shfl_xor_sync(0xffffffffu, v, o);
        if (lane == 0) atomicAdd(out, v * (1.0f / (float)NROWS));
    }
}

// ---------------- launch ----------------
extern "C" void kernel_launch(void* const* d_in, const int* in_sizes, int n_in,
                              void* d_out, int out_size) {
    const float* A = (const float*)d_in[0];
    const float* P = (const float*)d_in[1];
    prep_kernel<<<NROWS / 8, 256>>>(A, P, (float*)d_out);
    mma_kernel<<<dim3(NT, NT), 256>>>();
    loss_kernel<<<NROWS / 256, 256>>>((float*)d_out);
}

// round 8
// speedup vs baseline: 1.1059x; 1.1059x over previous
#include <cuda_runtime.h>
#include <cuda_bf16.h>
#include <cstdint>
#include <cmath>

#define NROWS 8192
#define XROWS 16384
#define DIM   64
#define BT    128                 // tile dim
#define NT    (XROWS / BT)        // 128 tiles per side
#define NTRI  (NT * (NT + 1) / 2) // 8256 upper-triangle tiles
#define LPAD  72                  // padded smem row stride (bf16): conflict-free ldmatrix

#define SCALE_L2E 28.853900817779268f   // 20 * log2(e)

// ---------------- device scratch ----------------
__device__ __align__(16) __nv_bfloat16 g_Xs[XROWS * DIM];  // normalized * 20*log2(e)
__device__ __align__(16) __nv_bfloat16 g_Xn[XROWS * DIM];  // normalized
__device__ float g_part[XROWS];
__device__ float g_pos[NROWS];

static __device__ __forceinline__ uint32_t smem_u32(const void* p) {
    uint32_t a;
    asm("{ .reg .u64 t; cvta.to.shared.u64 t, %1; cvt.u32.u64 %0, t; }" : "=r"(a) : "l"(p));
    return a;
}
static __device__ __forceinline__ float ex2f(float x) {
    float y; asm("ex2.approx.ftz.f32 %0, %1;" : "=f"(y) : "f"(x)); return y;
}

// ---------------- kernel 1: fused normalize + bf16 + exact pos logit + zeroing ----------------
__global__ void prep_kernel(const float* __restrict__ A, const float* __restrict__ P,
                            float* __restrict__ out) {
    int row  = blockIdx.x * 8 + (threadIdx.x >> 5);
    int lane = threadIdx.x & 31;
    float a0 = A[(size_t)row * DIM + lane], a1 = A[(size_t)row * DIM + lane + 32];
    float p0 = P[(size_t)row * DIM + lane], p1 = P[(size_t)row * DIM + lane + 32];
    float sa = a0 * a0 + a1 * a1;
    float sp = p0 * p0 + p1 * p1;
    float d  = a0 * p0 + a1 * p1;
    #pragma unroll
    for (int o = 16; o; o >>= 1) {
        sa += __shfl_xor_sync(0xffffffffu, sa, o);
        sp += __shfl_xor_sync(0xffffffffu, sp, o);
        d  += __shfl_xor_sync(0xffffffffu, d,  o);
    }
    float ra = rsqrtf(fmaxf(sa, 1e-24f));
    float rp = rsqrtf(fmaxf(sp, 1e-24f));
    float va0 = a0 * ra, va1 = a1 * ra;
    float vp0 = p0 * rp, vp1 = p1 * rp;
    size_t ia = (size_t)row * DIM, ip = (size_t)(row + NROWS) * DIM;
    g_Xn[ia + lane]      = __float2bfloat16(va0);
    g_Xn[ia + lane + 32] = __float2bfloat16(va1);
    g_Xn[ip + lane]      = __float2bfloat16(vp0);
    g_Xn[ip + lane + 32] = __float2bfloat16(vp1);
    g_Xs[ia + lane]      = __float2bfloat16(va0 * SCALE_L2E);
    g_Xs[ia + lane + 32] = __float2bfloat16(va1 * SCALE_L2E);
    g_Xs[ip + lane]      = __float2bfloat16(vp0 * SCALE_L2E);
    g_Xs[ip + lane + 32] = __float2bfloat16(vp1 * SCALE_L2E);
    if (lane == 0) {
        g_pos[row] = 20.0f * d / fmaxf(sqrtf(sa) * sqrtf(sp), 1e-6f);
        g_part[row] = 0.0f;
        g_part[row + NROWS] = 0.0f;
    }
    if (blockIdx.x == 0 && threadIdx.x == 0) out[0] = 0.0f;
}

// ---------------- kernel 2: upper-triangle tile GEMM + exp + row AND col sums ----------------
// One tile (bi,bj), bj>=bi, per CTA. Each exp credits part[row] (register row sum)
// and part[col] (register col partials cs[8][2], flushed twice per tile via shfl ->
// smem colsum -> one global atomic per column). Diagonal tiles: strict upper only
// (exactly replaces the -2*e^{1/T} self terms).
__global__ void __launch_bounds__(256, 2) mma_kernel() {
    __shared__ __nv_bfloat16 Ls[BT][LPAD];
    __shared__ __nv_bfloat16 Rs[BT][LPAD];
    __shared__ float colsum[BT];

    // decode linear index -> upper-triangle (bi, bj)
    int t = blockIdx.x;
    int bi = (int)((2.0 * NT + 1.0 - sqrt((2.0 * NT + 1.0) * (2.0 * NT + 1.0) - 8.0 * (double)t)) * 0.5);
    while ((bi + 1) * (2 * NT - bi) / 2 <= t) ++bi;
    while (bi * (2 * NT - bi + 1) / 2 > t) --bi;
    int bj = bi + (t - bi * (2 * NT - bi + 1) / 2);

    int tid = threadIdx.x, wid = tid >> 5, lane = tid & 31;

    const uint4* Lg = (const uint4*)(g_Xs + (size_t)bi * BT * DIM);
    const uint4* Rg = (const uint4*)(g_Xn + (size_t)bj * BT * DIM);
    #pragma unroll
    for (int it = 0; it < 4; ++it) {
        int f = tid + it * 256;        // 1024 uint4 per tile (8 per row)
        int r = f >> 3, kc = f & 7;
        *(uint4*)&Ls[r][kc * 8] = Lg[f];
        *(uint4*)&Rs[r][kc * 8] = Rg[f];
    }
    if (tid < BT) colsum[tid] = 0.0f;
    __syncthreads();

    bool diag = (bi == bj);
    int grow0 = bi * BT, gcol0 = bj * BT;
    int gid = lane >> 2, tig = lane & 3;

    // A fragments for this warp's 16-row strip (all of K=64)
    uint32_t a[4][4];
    {
        int r  = wid * 16 + (lane & 15);
        int kh = (lane >> 4) * 8;
        #pragma unroll
        for (int kc = 0; kc < 4; ++kc) {
            uint32_t addr = smem_u32(&Ls[r][kc * 16 + kh]);
            asm volatile("ldmatrix.sync.aligned.m8n8.x4.shared.b16 {%0,%1,%2,%3}, [%4];"
                         : "=r"(a[kc][0]), "=r"(a[kc][1]), "=r"(a[kc][2]), "=r"(a[kc][3])
                         : "r"(addr));
        }
    }

    int myrow0 = grow0 + wid * 16 + gid;   // rows for c0/c1
    int myrow1 = myrow0 + 8;               // rows for c2/c3
    float row0s = 0.0f, row1s = 0.0f;
    float cs[8][2];                        // col partials for 4 n2-groups (16 regs)
    #pragma unroll
    for (int i = 0; i < 8; ++i) { cs[i][0] = 0.0f; cs[i][1] = 0.0f; }

    // B x4-ldmatrix lane mapping: lanes 0-7 -> (u0,h0), 8-15 -> (u0,h1),
    //                             16-23 -> (u1,h0), 24-31 -> (u1,h1)
    int b_u = (lane >> 4) & 1;
    int b_h = (lane >> 3) & 1;
    int b_r = lane & 7;

    #pragma unroll
    for (int n2 = 0; n2 < 8; ++n2) {
        uint32_t b[2][4][2];   // [ngroup u][kc][khalf]
        #pragma unroll
        for (int kc = 0; kc < 4; ++kc) {
            uint32_t addr = smem_u32(&Rs[n2 * 16 + b_u * 8 + b_r][kc * 16 + b_h * 8]);
            asm volatile("ldmatrix.sync.aligned.m8n8.x4.shared.b16 {%0,%1,%2,%3}, [%4];"
                         : "=r"(b[0][kc][0]), "=r"(b[0][kc][1]),
                           "=r"(b[1][kc][0]), "=r"(b[1][kc][1])
                         : "r"(addr));
        }
        float c[2][4] = {};
        #pragma unroll
        for (int kc = 0; kc < 4; ++kc) {
            #pragma unroll
            for (int u = 0; u < 2; ++u) {
                asm volatile(
                    "mma.sync.aligned.m16n8k16.row.col.f32.bf16.bf16.f32 "
                    "{%0,%1,%2,%3}, {%4,%5,%6,%7}, {%8,%9}, {%0,%1,%2,%3};"
                    : "+f"(c[u][0]), "+f"(c[u][1]), "+f"(c[u][2]), "+f"(c[u][3])
                    : "r"(a[kc][0]), "r"(a[kc][1]), "r"(a[kc][2]), "r"(a[kc][3]),
                      "r"(b[u][kc][0]), "r"(b[u][kc][1]));
            }
        }
        #pragma unroll
        for (int u = 0; u < 2; ++u) {
            float e0 = ex2f(c[u][0]), e1 = ex2f(c[u][1]);
            float e2 = ex2f(c[u][2]), e3 = ex2f(c[u][3]);
            if (diag) {   // strict upper triangle only (removes -2*e^{1/T} terms exactly)
                int gc0 = gcol0 + (n2 * 2 + u) * 8 + tig * 2;
                if (gc0     <= myrow0) e0 = 0.0f;
                if (gc0 + 1 <= myrow0) e1 = 0.0f;
                if (gc0     <= myrow1) e2 = 0.0f;
                if (gc0 + 1 <= myrow1) e3 = 0.0f;
            }
            row0s += e0 + e1;
            row1s += e2 + e3;
            int ci = (n2 & 3) * 2 + u;
            cs[ci][0] += e0 + e2;
            cs[ci][1] += e1 + e3;
        }
        // flush col partials every 4 n2-groups (keeps live cs at 16 regs)
        if ((n2 & 3) == 3) {
            int base = (n2 >> 2) * 4;    // first n2 of this quad
            #pragma unroll
            for (int ci = 0; ci < 8; ++ci) {
                #pragma unroll
                for (int p = 0; p < 2; ++p) {
                    float v = cs[ci][p];
                    v += __shfl_xor_sync(0xffffffffu, v, 4);
                    v += __shfl_xor_sync(0xffffffffu, v, 8);
                    v += __shfl_xor_sync(0xffffffffu, v, 16);
                    if (gid == 0) {
                        int n = (base + (ci >> 1)) * 2 + (ci & 1);
                        atomicAdd(&colsum[n * 8 + tig * 2 + p], v);
                    }
                    cs[ci][p] = 0.0f;
                }
            }
        }
    }

    // per-tile row flush: reduce over the 4 tig lanes sharing each row
    #pragma unroll
    for (int o = 1; o < 4; o <<= 1) {
        row0s += __shfl_xor_sync(0xffffffffu, row0s, o);
        row1s += __shfl_xor_sync(0xffffffffu, row1s, o);
    }
    if (tig == 0) {
        atomicAdd(&g_part[myrow0], row0s);
        atomicAdd(&g_part[myrow1], row1s);
    }

    // col flush: one global atomic per column
    __syncthreads();
    if (tid < BT) atomicAdd(&g_part[gcol0 + tid], colsum[tid]);
}

// ---------------- kernel 3: loss reduction straight into d_out ----------------
__global__ void loss_kernel(float* __restrict__ out) {
    __shared__ float wsum[8];
    int i = blockIdx.x * 256 + threadIdx.x;
    float s = __logf(g_part[i] + g_part[i + NROWS]) - g_pos[i];
    #pragma unroll
    for (int o = 16; o; o >>= 1) s += __shfl_xor_sync(0xffffffffu, s, o);
    int wid = threadIdx.x >> 5, lane = threadIdx.x & 31;
    if (lane == 0) wsum[wid] = s;
    __syncthreads();
    if (wid == 0) {
        float v = (lane < 8) ? wsum[lane] : 0.0f;
        #pragma unroll
        for (int o = 4; o; o >>= 1) v += __shfl_xor_sync(0xffffffffu, v, o);
        if (lane == 0) atomicAdd(out, v * (1.0f / (float)NROWS));
    }
}

// ---------------- launch ----------------
extern "C" void kernel_launch(void* const* d_in, const int* in_sizes, int n_in,
                              void* d_out, int out_size) {
    const float* A = (const float*)d_in[0];
    const float* P = (const float*)d_in[1];
    prep_kernel<<<NROWS / 8, 256>>>(A, P, (float*)d_out);
    mma_kernel<<<NTRI, 256>>>();
    loss_kernel<<<NROWS / 256, 256>>>((float*)d_out);
}

// round 9
// speedup vs baseline: 1.8392x; 1.6631x over previous
#include <cuda_runtime.h>
#include <cuda_fp16.h>
#include <cstdint>
#include <cmath>

#define NROWS 8192
#define XROWS 16384
#define DIM   64
#define BT    128                 // tile dim
#define NT    (XROWS / BT)        // 128 tiles per side
#define LPAD  72                  // padded smem row stride (f16): conflict-free ldmatrix

#define SCALE_L2E 28.853900817779268f   // 20 * log2(e)

// ---------------- device scratch ----------------
__device__ __align__(16) __half g_Xs[XROWS * DIM];  // normalized * 20*log2(e)
__device__ __align__(16) __half g_Xn[XROWS * DIM];  // normalized
__device__ float g_part[XROWS];
__device__ float g_pos[NROWS];

static __device__ __forceinline__ uint32_t smem_u32(const void* p) {
    uint32_t a;
    asm("{ .reg .u64 t; cvta.to.shared.u64 t, %1; cvt.u32.u64 %0, t; }" : "=r"(a) : "l"(p));
    return a;
}
static __device__ __forceinline__ float ex2f(float x) {
    float y; asm("ex2.approx.ftz.f32 %0, %1;" : "=f"(y) : "f"(x)); return y;
}

// ---------------- kernel 1: fused normalize + f16 + exact pos logit + zeroing ----------------
__global__ void prep_kernel(const float* __restrict__ A, const float* __restrict__ P,
                            float* __restrict__ out) {
    int row  = blockIdx.x * 8 + (threadIdx.x >> 5);
    int lane = threadIdx.x & 31;
    float a0 = A[(size_t)row * DIM + lane], a1 = A[(size_t)row * DIM + lane + 32];
    float p0 = P[(size_t)row * DIM + lane], p1 = P[(size_t)row * DIM + lane + 32];
    float sa = a0 * a0 + a1 * a1;
    float sp = p0 * p0 + p1 * p1;
    float d  = a0 * p0 + a1 * p1;
    #pragma unroll
    for (int o = 16; o; o >>= 1) {
        sa += __shfl_xor_sync(0xffffffffu, sa, o);
        sp += __shfl_xor_sync(0xffffffffu, sp, o);
        d  += __shfl_xor_sync(0xffffffffu, d,  o);
    }
    float ra = rsqrtf(fmaxf(sa, 1e-24f));
    float rp = rsqrtf(fmaxf(sp, 1e-24f));
    float va0 = a0 * ra, va1 = a1 * ra;
    float vp0 = p0 * rp, vp1 = p1 * rp;
    size_t ia = (size_t)row * DIM, ip = (size_t)(row + NROWS) * DIM;
    g_Xn[ia + lane]      = __float2half(va0);
    g_Xn[ia + lane + 32] = __float2half(va1);
    g_Xn[ip + lane]      = __float2half(vp0);
    g_Xn[ip + lane + 32] = __float2half(vp1);
    g_Xs[ia + lane]      = __float2half(va0 * SCALE_L2E);
    g_Xs[ia + lane + 32] = __float2half(va1 * SCALE_L2E);
    g_Xs[ip + lane]      = __float2half(vp0 * SCALE_L2E);
    g_Xs[ip + lane + 32] = __float2half(vp1 * SCALE_L2E);
    if (lane == 0) {
        g_pos[row] = 20.0f * d / fmaxf(sqrtf(sa) * sqrtf(sp), 1e-6f);
        g_part[row] = 0.0f;
        g_part[row + NROWS] = 0.0f;
    }
    if (blockIdx.x == 0 && threadIdx.x == 0) out[0] = 0.0f;
}

// ---------------- kernel 2: full-grid tile GEMM (f16 accum) + exp + ROW sums ----------------
// Tile (bi,bj) of exp(20*cos(X,X)); f16 accumulators (|arg| <= 28.9, no overflow),
// summation of exps in fp32. Row sums only; global diagonal skipped (== -2*e^{1/T}).
__global__ void __launch_bounds__(256, 2) mma_kernel() {
    __shared__ __half Ls[BT][LPAD];
    __shared__ __half Rs[BT][LPAD];

    int bi = blockIdx.y, bj = blockIdx.x;
    int tid = threadIdx.x, wid = tid >> 5, lane = tid & 31;

    const uint4* Lg = (const uint4*)(g_Xs + (size_t)bi * BT * DIM);
    const uint4* Rg = (const uint4*)(g_Xn + (size_t)bj * BT * DIM);
    #pragma unroll
    for (int it = 0; it < 4; ++it) {
        int f = tid + it * 256;        // 1024 uint4 per tile (8 per row)
        int r = f >> 3, kc = f & 7;
        *(uint4*)&Ls[r][kc * 8] = Lg[f];
        *(uint4*)&Rs[r][kc * 8] = Rg[f];
    }
    __syncthreads();

    bool diag = (bi == bj);
    int grow0 = bi * BT, gcol0 = bj * BT;
    int gid = lane >> 2, tig = lane & 3;

    // A fragments for this warp's 16-row strip (all of K=64)
    uint32_t a[4][4];
    {
        int r  = wid * 16 + (lane & 15);
        int kh = (lane >> 4) * 8;
        #pragma unroll
        for (int kc = 0; kc < 4; ++kc) {
            uint32_t addr = smem_u32(&Ls[r][kc * 16 + kh]);
            asm volatile("ldmatrix.sync.aligned.m8n8.x4.shared.b16 {%0,%1,%2,%3}, [%4];"
                         : "=r"(a[kc][0]), "=r"(a[kc][1]), "=r"(a[kc][2]), "=r"(a[kc][3])
                         : "r"(addr));
        }
    }

    int myrow0 = grow0 + wid * 16 + gid;   // rows for d0 halves
    int myrow1 = myrow0 + 8;               // rows for d1 halves
    float row0s = 0.0f, row1s = 0.0f;

    // B x4-ldmatrix lane mapping: lanes 0-7 -> (u0,h0), 8-15 -> (u0,h1),
    //                             16-23 -> (u1,h0), 24-31 -> (u1,h1)
    int b_u = (lane >> 4) & 1;
    int b_h = (lane >> 3) & 1;
    int b_r = lane & 7;

    #pragma unroll
    for (int n2 = 0; n2 < 8; ++n2) {
        uint32_t b[2][4][2];   // [ngroup u][kc][khalf]
        #pragma unroll
        for (int kc = 0; kc < 4; ++kc) {
            uint32_t addr = smem_u32(&Rs[n2 * 16 + b_u * 8 + b_r][kc * 16 + b_h * 8]);
            asm volatile("ldmatrix.sync.aligned.m8n8.x4.shared.b16 {%0,%1,%2,%3}, [%4];"
                         : "=r"(b[0][kc][0]), "=r"(b[0][kc][1]),
                           "=r"(b[1][kc][0]), "=r"(b[1][kc][1])
                         : "r"(addr));
        }
        uint32_t c[2][2] = {{0u, 0u}, {0u, 0u}};   // packed half2 accumulators
        #pragma unroll
        for (int kc = 0; kc < 4; ++kc) {
            #pragma unroll
            for (int u = 0; u < 2; ++u) {
                asm volatile(
                    "mma.sync.aligned.m16n8k16.row.col.f16.f16.f16.f16 "
                    "{%0,%1}, {%2,%3,%4,%5}, {%6,%7}, {%0,%1};"
                    : "+r"(c[u][0]), "+r"(c[u][1])
                    : "r"(a[kc][0]), "r"(a[kc][1]), "r"(a[kc][2]), "r"(a[kc][3]),
                      "r"(b[u][kc][0]), "r"(b[u][kc][1]));
            }
        }
        #pragma unroll
        for (int u = 0; u < 2; ++u) {
            float2 f0 = __half22float2(*reinterpret_cast<__half2*>(&c[u][0]));
            float2 f1 = __half22float2(*reinterpret_cast<__half2*>(&c[u][1]));
            float e0 = ex2f(f0.x), e1 = ex2f(f0.y);
            float e2 = ex2f(f1.x), e3 = ex2f(f1.y);
            if (diag) {   // zero the single global-diagonal element
                int gc0 = gcol0 + (n2 * 2 + u) * 8 + tig * 2;
                if (gc0     == myrow0) e0 = 0.0f;
                if (gc0 + 1 == myrow0) e1 = 0.0f;
                if (gc0     == myrow1) e2 = 0.0f;
                if (gc0 + 1 == myrow1) e3 = 0.0f;
            }
            row0s += e0 + e1;
            row1s += e2 + e3;
        }
    }

    // reduce over the 4 lanes (tig) sharing each row, then global accumulate
    #pragma unroll
    for (int o = 1; o < 4; o <<= 1) {
        row0s += __shfl_xor_sync(0xffffffffu, row0s, o);
        row1s += __shfl_xor_sync(0xffffffffu, row1s, o);
    }
    if (tig == 0) {
        atomicAdd(&g_part[myrow0], row0s);
        atomicAdd(&g_part[myrow1], row1s);
    }
}

// ---------------- kernel 3: loss reduction straight into d_out ----------------
__global__ void loss_kernel(float* __restrict__ out) {
    __shared__ float wsum[8];
    int i = blockIdx.x * 256 + threadIdx.x;
    float s = __logf(g_part[i] + g_part[i + NROWS]) - g_pos[i];
    #pragma unroll
    for (int o = 16; o; o >>= 1) s += __shfl_xor_sync(0xffffffffu, s, o);
    int wid = threadIdx.x >> 5, lane = threadIdx.x & 31;
    if (lane == 0) wsum[wid] = s;
    __syncthreads();
    if (wid == 0) {
        float v = (lane < 8) ? wsum[lane] : 0.0f;
        #pragma unroll
        for (int o = 4; o; o >>= 1) v += __shfl_xor_sync(0xffffffffu, v, o);
        if (lane == 0) atomicAdd(out, v * (1.0f / (float)NROWS));
    }
}

// ---------------- launch ----------------
extern "C" void kernel_launch(void* const* d_in, const int* in_sizes, int n_in,
                              void* d_out, int out_size) {
    const float* A = (const float*)d_in[0];
    const float* P = (const float*)d_in[1];
    prep_kernel<<<NROWS / 8, 256>>>(A, P, (float*)d_out);
    mma_kernel<<<dim3(NT, NT), 256>>>();
    loss_kernel<<<NROWS / 256, 256>>>((float*)d_out);
}

// round 10
// speedup vs baseline: 2.0316x; 1.1046x over previous
#include <cuda_runtime.h>
#include <cuda_bf16.h>
#include <cstdint>
#include <cmath>

#define NROWS 8192
#define XROWS 16384
#define DIM   64
#define BT    128                 // tile dim
#define NT    (XROWS / BT)        // 128 tiles per side
#define NTRI  (NT * (NT + 1) / 2) // 8256 upper-triangle tiles
#define LPAD  72                  // padded smem row stride (bf16): conflict-free ldmatrix
#define CPAD  132                 // colpart row stride (floats)

#define SCALE_L2E 28.853900817779268f   // 20 * log2(e)

// ---------------- device scratch ----------------
__device__ __align__(16) __nv_bfloat16 g_Xs[XROWS * DIM];  // normalized * 20*log2(e)
__device__ __align__(16) __nv_bfloat16 g_Xn[XROWS * DIM];  // normalized
__device__ float g_part[XROWS];
__device__ float g_pos[NROWS];

static __device__ __forceinline__ uint32_t smem_u32(const void* p) {
    uint32_t a;
    asm("{ .reg .u64 t; cvta.to.shared.u64 t, %1; cvt.u32.u64 %0, t; }" : "=r"(a) : "l"(p));
    return a;
}
static __device__ __forceinline__ float ex2f(float x) {
    float y; asm("ex2.approx.ftz.f32 %0, %1;" : "=f"(y) : "f"(x)); return y;
}

// ---------------- kernel 1: fused normalize + bf16 + exact pos logit + zeroing ----------------
__global__ void prep_kernel(const float* __restrict__ A, const float* __restrict__ P,
                            float* __restrict__ out) {
    int row  = blockIdx.x * 8 + (threadIdx.x >> 5);
    int lane = threadIdx.x & 31;
    float a0 = A[(size_t)row * DIM + lane], a1 = A[(size_t)row * DIM + lane + 32];
    float p0 = P[(size_t)row * DIM + lane], p1 = P[(size_t)row * DIM + lane + 32];
    float sa = a0 * a0 + a1 * a1;
    float sp = p0 * p0 + p1 * p1;
    float d  = a0 * p0 + a1 * p1;
    #pragma unroll
    for (int o = 16; o; o >>= 1) {
        sa += __shfl_xor_sync(0xffffffffu, sa, o);
        sp += __shfl_xor_sync(0xffffffffu, sp, o);
        d  += __shfl_xor_sync(0xffffffffu, d,  o);
    }
    float ra = rsqrtf(fmaxf(sa, 1e-24f));
    float rp = rsqrtf(fmaxf(sp, 1e-24f));
    float va0 = a0 * ra, va1 = a1 * ra;
    float vp0 = p0 * rp, vp1 = p1 * rp;
    size_t ia = (size_t)row * DIM, ip = (size_t)(row + NROWS) * DIM;
    g_Xn[ia + lane]      = __float2bfloat16(va0);
    g_Xn[ia + lane + 32] = __float2bfloat16(va1);
    g_Xn[ip + lane]      = __float2bfloat16(vp0);
    g_Xn[ip + lane + 32] = __float2bfloat16(vp1);
    g_Xs[ia + lane]      = __float2bfloat16(va0 * SCALE_L2E);
    g_Xs[ia + lane + 32] = __float2bfloat16(va1 * SCALE_L2E);
    g_Xs[ip + lane]      = __float2bfloat16(vp0 * SCALE_L2E);
    g_Xs[ip + lane + 32] = __float2bfloat16(vp1 * SCALE_L2E);
    if (lane == 0) {
        g_pos[row] = 20.0f * d / fmaxf(sqrtf(sa) * sqrtf(sp), 1e-6f);
        g_part[row] = 0.0f;
        g_part[row + NROWS] = 0.0f;
    }
    if (blockIdx.x == 0 && threadIdx.x == 0) out[0] = 0.0f;
}

// ---------------- kernel 2: upper-triangle tile GEMM + exp + row & col sums ----------------
// One tile (bi,bj), bj>=bi, per CTA. R5 mainloop; col partials accumulate in 32
// registers (no cross-lane traffic), flushed ONCE at tile end into smem staging
// that overlays the dead Ls/Rs, then column-reduced with plain LDS. Diagonal
// tiles keep strict upper only (exactly replaces the -2*e^{1/T} self terms).
__global__ void __launch_bounds__(256, 2) mma_kernel() {
    __shared__ __align__(16) unsigned char ubuf[BT * LPAD * 2 * sizeof(__nv_bfloat16)];
    __nv_bfloat16 (*Ls)[LPAD] = reinterpret_cast<__nv_bfloat16 (*)[LPAD]>(ubuf);
    __nv_bfloat16 (*Rs)[LPAD] = reinterpret_cast<__nv_bfloat16 (*)[LPAD]>(ubuf + BT * LPAD * sizeof(__nv_bfloat16));
    float (*colpart)[CPAD]    = reinterpret_cast<float (*)[CPAD]>(ubuf);   // 64*132*4 = 33792 <= 36864

    // decode linear index -> upper-triangle (bi, bj)
    int t = blockIdx.x;
    int bi = (int)((2.0 * NT + 1.0 - sqrt((2.0 * NT + 1.0) * (2.0 * NT + 1.0) - 8.0 * (double)t)) * 0.5);
    while ((bi + 1) * (2 * NT - bi) / 2 <= t) ++bi;
    while (bi * (2 * NT - bi + 1) / 2 > t) --bi;
    int bj = bi + (t - bi * (2 * NT - bi + 1) / 2);

    int tid = threadIdx.x, wid = tid >> 5, lane = tid & 31;

    const uint4* Lg = (const uint4*)(g_Xs + (size_t)bi * BT * DIM);
    const uint4* Rg = (const uint4*)(g_Xn + (size_t)bj * BT * DIM);
    #pragma unroll
    for (int it = 0; it < 4; ++it) {
        int f = tid + it * 256;        // 1024 uint4 per tile (8 per row)
        int r = f >> 3, kc = f & 7;
        *(uint4*)&Ls[r][kc * 8] = Lg[f];
        *(uint4*)&Rs[r][kc * 8] = Rg[f];
    }
    __syncthreads();

    bool diag = (bi == bj);
    int grow0 = bi * BT, gcol0 = bj * BT;
    int gid = lane >> 2, tig = lane & 3;

    // A fragments for this warp's 16-row strip (all of K=64)
    uint32_t a[4][4];
    {
        int r  = wid * 16 + (lane & 15);
        int kh = (lane >> 4) * 8;
        #pragma unroll
        for (int kc = 0; kc < 4; ++kc) {
            uint32_t addr = smem_u32(&Ls[r][kc * 16 + kh]);
            asm volatile("ldmatrix.sync.aligned.m8n8.x4.shared.b16 {%0,%1,%2,%3}, [%4];"
                         : "=r"(a[kc][0]), "=r"(a[kc][1]), "=r"(a[kc][2]), "=r"(a[kc][3])
                         : "r"(addr));
        }
    }

    int myrow0 = grow0 + wid * 16 + gid;   // rows for c0/c1
    int myrow1 = myrow0 + 8;               // rows for c2/c3
    float row0s = 0.0f, row1s = 0.0f;
    float cs[16][2];                       // per-thread col partials (32 regs, static idx)
    #pragma unroll
    for (int i = 0; i < 16; ++i) { cs[i][0] = 0.0f; cs[i][1] = 0.0f; }

    // B x4-ldmatrix lane mapping: lanes 0-7 -> (u0,h0), 8-15 -> (u0,h1),
    //                             16-23 -> (u1,h0), 24-31 -> (u1,h1)
    int b_u = (lane >> 4) & 1;
    int b_h = (lane >> 3) & 1;
    int b_r = lane & 7;

    #pragma unroll
    for (int n2 = 0; n2 < 8; ++n2) {
        uint32_t b[2][4][2];   // [ngroup u][kc][khalf]
        #pragma unroll
        for (int kc = 0; kc < 4; ++kc) {
            uint32_t addr = smem_u32(&Rs[n2 * 16 + b_u * 8 + b_r][kc * 16 + b_h * 8]);
            asm volatile("ldmatrix.sync.aligned.m8n8.x4.shared.b16 {%0,%1,%2,%3}, [%4];"
                         : "=r"(b[0][kc][0]), "=r"(b[0][kc][1]),
                           "=r"(b[1][kc][0]), "=r"(b[1][kc][1])
                         : "r"(addr));
        }
        float c[2][4] = {};
        #pragma unroll
        for (int kc = 0; kc < 4; ++kc) {
            #pragma unroll
            for (int u = 0; u < 2; ++u) {
                asm volatile(
                    "mma.sync.aligned.m16n8k16.row.col.f32.bf16.bf16.f32 "
                    "{%0,%1,%2,%3}, {%4,%5,%6,%7}, {%8,%9}, {%0,%1,%2,%3};"
                    : "+f"(c[u][0]), "+f"(c[u][1]), "+f"(c[u][2]), "+f"(c[u][3])
                    : "r"(a[kc][0]), "r"(a[kc][1]), "r"(a[kc][2]), "r"(a[kc][3]),
                      "r"(b[u][kc][0]), "r"(b[u][kc][1]));
            }
        }
        #pragma unroll
        for (int u = 0; u < 2; ++u) {
            float e0 = ex2f(c[u][0]), e1 = ex2f(c[u][1]);
            float e2 = ex2f(c[u][2]), e3 = ex2f(c[u][3]);
            if (diag) {   // strict upper triangle only (removes -2*e^{1/T} exactly)
                int gc0 = gcol0 + (n2 * 2 + u) * 8 + tig * 2;
                if (gc0     <= myrow0) e0 = 0.0f;
                if (gc0 + 1 <= myrow0) e1 = 0.0f;
                if (gc0     <= myrow1) e2 = 0.0f;
                if (gc0 + 1 <= myrow1) e3 = 0.0f;
            }
            row0s += e0 + e1;
            row1s += e2 + e3;
            int ci = n2 * 2 + u;           // compile-time constant
            cs[ci][0] += e0 + e2;
            cs[ci][1] += e1 + e3;
        }
    }

    // row flush: reduce over the 4 tig lanes sharing each row (4 shfl total)
    #pragma unroll
    for (int o = 1; o < 4; o <<= 1) {
        row0s += __shfl_xor_sync(0xffffffffu, row0s, o);
        row1s += __shfl_xor_sync(0xffffffffu, row1s, o);
    }
    if (tig == 0) {
        atomicAdd(&g_part[myrow0], row0s);
        atomicAdd(&g_part[myrow1], row1s);
    }

    // ---- col flush: overlay staging (Ls/Rs dead now) ----
    __syncthreads();                       // all warps done reading Ls/Rs
    {
        int slice = wid * 8 + gid;         // 0..63
        #pragma unroll
        for (int ci = 0; ci < 16; ++ci) {
            // col pair (ci*8 + tig*2, +1): one aligned float2 store, no reduction
            *(float2*)&colpart[slice][ci * 8 + tig * 2] = make_float2(cs[ci][0], cs[ci][1]);
        }
    }
    __syncthreads();
    {
        int col = tid & 127, h = tid >> 7;   // 2 threads per column
        float s = 0.0f;
        #pragma unroll
        for (int k = 0; k < 32; ++k) s += colpart[h * 32 + k][col];
        atomicAdd(&g_part[gcol0 + col], s);
    }
}

// ---------------- kernel 3: loss reduction straight into d_out ----------------
__global__ void loss_kernel(float* __restrict__ out) {
    __shared__ float wsum[8];
    int i = blockIdx.x * 256 + threadIdx.x;
    float s = __logf(g_part[i] + g_part[i + NROWS]) - g_pos[i];
    #pragma unroll
    for (int o = 16; o; o >>= 1) s += __shfl_xor_sync(0xffffffffu, s, o);
    int wid = threadIdx.x >> 5, lane = threadIdx.x & 31;
    if (lane == 0) wsum[wid] = s;
    __syncthreads();
    if (wid == 0) {
        float v = (lane < 8) ? wsum[lane] : 0.0f;
        #pragma unroll
        for (int o = 4; o; o >>= 1) v += __shfl_xor_sync(0xffffffffu, v, o);
        if (lane == 0) atomicAdd(out, v * (1.0f / (float)NROWS));
    }
}

// ---------------- launch ----------------
extern "C" void kernel_launch(void* const* d_in, const int* in_sizes, int n_in,
                              void* d_out, int out_size) {
    const float* A = (const float*)d_in[0];
    const float* P = (const float*)d_in[1];
    prep_kernel<<<NROWS / 8, 256>>>(A, P, (float*)d_out);
    mma_kernel<<<NTRI, 256>>>();
    loss_kernel<<<NROWS / 256, 256>>>((float*)d_out);
}

// round 11
// speedup vs baseline: 2.1050x; 1.0361x over previous
#include <cuda_runtime.h>
#include <cuda_bf16.h>
#include <cstdint>
#include <cmath>

#define NROWS 8192
#define XROWS 16384
#define DIM   64
#define BT    128                 // tile dim
#define NT    (XROWS / BT)        // 128 tiles per side
#define NTRI  (NT * (NT + 1) / 2) // 8256 upper-triangle tiles
#define LPAD  72                  // padded smem row stride (bf16 elems)
#define ROWB  (LPAD * 2)          // 144 bytes per smem row
#define TILEB (BT * ROWB)         // 18432 bytes per operand tile
#define BUFB  (2 * TILEB)         // 36864 bytes per double-buffer slot (Ls+Rs)
#define CPOFF (2 * BUFB)          // colpart offset: 73728
#define CPAD  132                 // colpart row stride (floats)
#define SMEM_TOTAL (CPOFF + 64 * CPAD * 4)   // 107520 bytes

#define SCALE_L2E 28.853900817779268f   // 20 * log2(e)

// ---------------- device scratch ----------------
__device__ __align__(16) __nv_bfloat16 g_Xs[XROWS * DIM];  // normalized * 20*log2(e)
__device__ __align__(16) __nv_bfloat16 g_Xn[XROWS * DIM];  // normalized
__device__ float g_part[XROWS];
__device__ float g_pos[NROWS];

static __device__ __forceinline__ uint32_t smem_u32(const void* p) {
    uint32_t a;
    asm("{ .reg .u64 t; cvta.to.shared.u64 t, %1; cvt.u32.u64 %0, t; }" : "=r"(a) : "l"(p));
    return a;
}
static __device__ __forceinline__ float ex2f(float x) {
    float y; asm("ex2.approx.ftz.f32 %0, %1;" : "=f"(y) : "f"(x)); return y;
}
static __device__ __forceinline__ void cp16(uint32_t dst, const void* src) {
    asm volatile("cp.async.cg.shared.global [%0], [%1], 16;" :: "r"(dst), "l"(src) : "memory");
}
static __device__ __forceinline__ void decode_tri(int t, int& bi, int& bj) {
    int est = (int)((2.0 * NT + 1.0 - sqrt((2.0 * NT + 1.0) * (2.0 * NT + 1.0) - 8.0 * (double)t)) * 0.5);
    if (est > NT - 1) est = NT - 1;
    if (est < 0) est = 0;
    while ((est + 1) * (2 * NT - est) / 2 <= t) ++est;
    while (est * (2 * NT - est + 1) / 2 > t) --est;
    bi = est;
    bj = est + (t - est * (2 * NT - est + 1) / 2);
}

// ---------------- kernel 1: fused normalize + bf16 + exact pos logit + zeroing ----------------
__global__ void prep_kernel(const float* __restrict__ A, const float* __restrict__ P,
                            float* __restrict__ out) {
    int row  = blockIdx.x * 8 + (threadIdx.x >> 5);
    int lane = threadIdx.x & 31;
    float a0 = A[(size_t)row * DIM + lane], a1 = A[(size_t)row * DIM + lane + 32];
    float p0 = P[(size_t)row * DIM + lane], p1 = P[(size_t)row * DIM + lane + 32];
    float sa = a0 * a0 + a1 * a1;
    float sp = p0 * p0 + p1 * p1;
    float d  = a0 * p0 + a1 * p1;
    #pragma unroll
    for (int o = 16; o; o >>= 1) {
        sa += __shfl_xor_sync(0xffffffffu, sa, o);
        sp += __shfl_xor_sync(0xffffffffu, sp, o);
        d  += __shfl_xor_sync(0xffffffffu, d,  o);
    }
    float ra = rsqrtf(fmaxf(sa, 1e-24f));
    float rp = rsqrtf(fmaxf(sp, 1e-24f));
    float va0 = a0 * ra, va1 = a1 * ra;
    float vp0 = p0 * rp, vp1 = p1 * rp;
    size_t ia = (size_t)row * DIM, ip = (size_t)(row + NROWS) * DIM;
    g_Xn[ia + lane]      = __float2bfloat16(va0);
    g_Xn[ia + lane + 32] = __float2bfloat16(va1);
    g_Xn[ip + lane]      = __float2bfloat16(vp0);
    g_Xn[ip + lane + 32] = __float2bfloat16(vp1);
    g_Xs[ia + lane]      = __float2bfloat16(va0 * SCALE_L2E);
    g_Xs[ia + lane + 32] = __float2bfloat16(va1 * SCALE_L2E);
    g_Xs[ip + lane]      = __float2bfloat16(vp0 * SCALE_L2E);
    g_Xs[ip + lane + 32] = __float2bfloat16(vp1 * SCALE_L2E);
    if (lane == 0) {
        g_pos[row] = 20.0f * d / fmaxf(sqrtf(sa) * sqrtf(sp), 1e-6f);
        g_part[row] = 0.0f;
        g_part[row + NROWS] = 0.0f;
    }
    if (blockIdx.x == 0 && threadIdx.x == 0) out[0] = 0.0f;
}

// ---------------- kernel 2: persistent upper-triangle GEMM, cp.async double-buffered ----------------
// Each CTA walks tiles t, t+G, ... of the triangle; next tile's Ls/Rs prefetched
// into the alternate buffer during compute. Mainloop/epilogue identical to R10.
// Diagonal tiles keep strict upper only (exactly replaces the -2*e^{1/T} terms).
__global__ void __launch_bounds__(256, 2) mma_kernel(int G) {
    extern __shared__ __align__(16) unsigned char smem[];
    uint32_t sbase = smem_u32(smem);
    float* colpart = (float*)(smem + CPOFF);

    int tid = threadIdx.x, wid = tid >> 5, lane = tid & 31;
    int gid = lane >> 2, tig = lane & 3;

    int t = blockIdx.x;
    if (t >= NTRI) return;

    int bi, bj;
    decode_tri(t, bi, bj);

    // prefetch first tile into buffer 0
    {
        const uint4* Lg = (const uint4*)(g_Xs + (size_t)bi * BT * DIM);
        const uint4* Rg = (const uint4*)(g_Xn + (size_t)bj * BT * DIM);
        #pragma unroll
        for (int it = 0; it < 4; ++it) {
            int f = tid + it * 256;
            uint32_t off = (uint32_t)(f >> 3) * ROWB + (uint32_t)(f & 7) * 16;
            cp16(sbase + off, Lg + f);
            cp16(sbase + TILEB + off, Rg + f);
        }
        asm volatile("cp.async.commit_group;" ::: "memory");
    }

    int buf = 0;
    for (; t < NTRI; t += G) {
        int tn = t + G;
        bool has_next = tn < NTRI;
        int bin, bjn;
        if (has_next) {
            decode_tri(tn, bin, bjn);
            uint32_t nb = sbase + (uint32_t)(buf ^ 1) * BUFB;
            const uint4* Lg = (const uint4*)(g_Xs + (size_t)bin * BT * DIM);
            const uint4* Rg = (const uint4*)(g_Xn + (size_t)bjn * BT * DIM);
            #pragma unroll
            for (int it = 0; it < 4; ++it) {
                int f = tid + it * 256;
                uint32_t off = (uint32_t)(f >> 3) * ROWB + (uint32_t)(f & 7) * 16;
                cp16(nb + off, Lg + f);
                cp16(nb + TILEB + off, Rg + f);
            }
            asm volatile("cp.async.commit_group;" ::: "memory");
            asm volatile("cp.async.wait_group 1;" ::: "memory");
        } else {
            asm volatile("cp.async.wait_group 0;" ::: "memory");
        }
        __syncthreads();   // current buffer ready for everyone; also separates
                           // prev iteration's colpart reads from this iter's writes

        uint32_t Lbase = sbase + (uint32_t)buf * BUFB;
        uint32_t Rbase = Lbase + TILEB;
        bool diag = (bi == bj);
        int grow0 = bi * BT, gcol0 = bj * BT;

        // A fragments for this warp's 16-row strip (all of K=64)
        uint32_t a[4][4];
        {
            int r  = wid * 16 + (lane & 15);
            int kh = (lane >> 4) * 8;
            #pragma unroll
            for (int kc = 0; kc < 4; ++kc) {
                uint32_t addr = Lbase + (uint32_t)r * ROWB + (uint32_t)(kc * 16 + kh) * 2;
                asm volatile("ldmatrix.sync.aligned.m8n8.x4.shared.b16 {%0,%1,%2,%3}, [%4];"
                             : "=r"(a[kc][0]), "=r"(a[kc][1]), "=r"(a[kc][2]), "=r"(a[kc][3])
                             : "r"(addr));
            }
        }

        int myrow0 = grow0 + wid * 16 + gid;
        int myrow1 = myrow0 + 8;
        float row0s = 0.0f, row1s = 0.0f;
        float cs[16][2];
        #pragma unroll
        for (int i = 0; i < 16; ++i) { cs[i][0] = 0.0f; cs[i][1] = 0.0f; }

        int b_u = (lane >> 4) & 1;
        int b_h = (lane >> 3) & 1;
        int b_r = lane & 7;

        #pragma unroll
        for (int n2 = 0; n2 < 8; ++n2) {
            uint32_t b[2][4][2];
            #pragma unroll
            for (int kc = 0; kc < 4; ++kc) {
                uint32_t addr = Rbase + (uint32_t)(n2 * 16 + b_u * 8 + b_r) * ROWB
                              + (uint32_t)(kc * 16 + b_h * 8) * 2;
                asm volatile("ldmatrix.sync.aligned.m8n8.x4.shared.b16 {%0,%1,%2,%3}, [%4];"
                             : "=r"(b[0][kc][0]), "=r"(b[0][kc][1]),
                               "=r"(b[1][kc][0]), "=r"(b[1][kc][1])
                             : "r"(addr));
            }
            float c[2][4] = {};
            #pragma unroll
            for (int kc = 0; kc < 4; ++kc) {
                #pragma unroll
                for (int u = 0; u < 2; ++u) {
                    asm volatile(
                        "mma.sync.aligned.m16n8k16.row.col.f32.bf16.bf16.f32 "
                        "{%0,%1,%2,%3}, {%4,%5,%6,%7}, {%8,%9}, {%0,%1,%2,%3};"
                        : "+f"(c[u][0]), "+f"(c[u][1]), "+f"(c[u][2]), "+f"(c[u][3])
                        : "r"(a[kc][0]), "r"(a[kc][1]), "r"(a[kc][2]), "r"(a[kc][3]),
                          "r"(b[u][kc][0]), "r"(b[u][kc][1]));
                }
            }
            #pragma unroll
            for (int u = 0; u < 2; ++u) {
                float e0 = ex2f(c[u][0]), e1 = ex2f(c[u][1]);
                float e2 = ex2f(c[u][2]), e3 = ex2f(c[u][3]);
                if (diag) {   // strict upper triangle only
                    int gc0 = gcol0 + (n2 * 2 + u) * 8 + tig * 2;
                    if (gc0     <= myrow0) e0 = 0.0f;
                    if (gc0 + 1 <= myrow0) e1 = 0.0f;
                    if (gc0     <= myrow1) e2 = 0.0f;
                    if (gc0 + 1 <= myrow1) e3 = 0.0f;
                }
                row0s += e0 + e1;
                row1s += e2 + e3;
                int ci = n2 * 2 + u;
                cs[ci][0] += e0 + e2;
                cs[ci][1] += e1 + e3;
            }
        }

        // row flush: 4 shfl + 2 spread atomics
        #pragma unroll
        for (int o = 1; o < 4; o <<= 1) {
            row0s += __shfl_xor_sync(0xffffffffu, row0s, o);
            row1s += __shfl_xor_sync(0xffffffffu, row1s, o);
        }
        if (tig == 0) {
            atomicAdd(&g_part[myrow0], row0s);
            atomicAdd(&g_part[myrow1], row1s);
        }

        // col flush: stage per-thread partials, then 2-thread-per-column reduce
        __syncthreads();
        {
            int slice = wid * 8 + gid;   // 0..63
            #pragma unroll
            for (int ci = 0; ci < 16; ++ci)
                *(float2*)&colpart[slice * CPAD + ci * 8 + tig * 2] = make_float2(cs[ci][0], cs[ci][1]);
        }
        __syncthreads();
        {
            int col = tid & 127, h = tid >> 7;
            float s = 0.0f;
            #pragma unroll
            for (int k = 0; k < 32; ++k) s += colpart[(h * 32 + k) * CPAD + col];
            atomicAdd(&g_part[gcol0 + col], s);
        }

        bi = bin; bj = bjn;
        buf ^= 1;
    }
}

// ---------------- kernel 3: loss reduction straight into d_out ----------------
__global__ void loss_kernel(float* __restrict__ out) {
    __shared__ float wsum[8];
    int i = blockIdx.x * 256 + threadIdx.x;
    float s = __logf(g_part[i] + g_part[i + NROWS]) - g_pos[i];
    #pragma unroll
    for (int o = 16; o; o >>= 1) s += __shfl_xor_sync(0xffffffffu, s, o);
    int wid = threadIdx.x >> 5, lane = threadIdx.x & 31;
    if (lane == 0) wsum[wid] = s;
    __syncthreads();
    if (wid == 0) {
        float v = (lane < 8) ? wsum[lane] : 0.0f;
        #pragma unroll
        for (int o = 4; o; o >>= 1) v += __shfl_xor_sync(0xffffffffu, v, o);
        if (lane == 0) atomicAdd(out, v * (1.0f / (float)NROWS));
    }
}

// ---------------- launch ----------------
extern "C" void kernel_launch(void* const* d_in, const int* in_sizes, int n_in,
                              void* d_out, int out_size) {
    const float* A = (const float*)d_in[0];
    const float* P = (const float*)d_in[1];
    int dev = 0, nsm = 148;
    cudaGetDevice(&dev);
    cudaDeviceGetAttribute(&nsm, cudaDevAttrMultiProcessorCount, dev);
    int G = nsm * 2;
    cudaFuncSetAttribute(mma_kernel, cudaFuncAttributeMaxDynamicSharedMemorySize, SMEM_TOTAL);
    prep_kernel<<<NROWS / 8, 256>>>(A, P, (float*)d_out);
    mma_kernel<<<G, 256, SMEM_TOTAL>>>(G);
    loss_kernel<<<NROWS / 256, 256>>>((float*)d_out);
}

// round 12
// speedup vs baseline: 3.2956x; 1.5656x over previous
#include <cuda_runtime.h>
#include <cuda_bf16.h>
#include <cstdint>
#include <cmath>

#define NROWS 8192
#define XROWS 16384
#define DIM   64
#define BT    128                 // tile dim
#define NT    (XROWS / BT)        // 128 tiles per side
#define NTRI  (NT * (NT + 1) / 2) // 8256 upper-triangle tiles
#define LPAD  72                  // padded smem row stride (bf16 elems)
#define ROWB  (LPAD * 2)          // 144 bytes per smem row
#define TILEB (BT * ROWB)         // 18432 bytes per operand tile
#define RSOFF (2 * TILEB)         // Rs slot after double-buffered Ls
#define CPOFF (3 * TILEB)         // colpart offset: 55296
#define CPAD  132                 // colpart row stride (floats)
#define SMEM_TOTAL (CPOFF + 64 * CPAD * 4)   // 89088 bytes

#define SCALE_L2E 28.853900817779268f   // 20 * log2(e)

// ---------------- device scratch ----------------
__device__ __align__(16) __nv_bfloat16 g_Xs[XROWS * DIM];  // normalized * 20*log2(e)
__device__ __align__(16) __nv_bfloat16 g_Xn[XROWS * DIM];  // normalized
__device__ float g_part[XROWS];
__device__ float g_pos[NROWS];

static __device__ __forceinline__ uint32_t smem_u32(const void* p) {
    uint32_t a;
    asm("{ .reg .u64 t; cvta.to.shared.u64 t, %1; cvt.u32.u64 %0, t; }" : "=r"(a) : "l"(p));
    return a;
}
static __device__ __forceinline__ float ex2f(float x) {
    float y; asm("ex2.approx.ftz.f32 %0, %1;" : "=f"(y) : "f"(x)); return y;
}
static __device__ __forceinline__ void cp16(uint32_t dst, const void* src) {
    asm volatile("cp.async.cg.shared.global [%0], [%1], 16;" :: "r"(dst), "l"(src) : "memory");
}
// column-major triangle: t = bj*(bj+1)/2 + bi, 0 <= bi <= bj
static __device__ __forceinline__ int col_of(int t) {
    int bj = (int)((sqrtf(8.0f * (float)t + 1.0f) - 1.0f) * 0.5f);
    if (bj < 0) bj = 0;
    if (bj > NT - 1) bj = NT - 1;
    while (bj * (bj + 1) / 2 > t) --bj;
    while ((bj + 1) * (bj + 2) / 2 <= t) ++bj;
    return bj;
}

// ---------------- kernel 1: fused normalize + bf16 + exact pos logit + zeroing ----------------
__global__ void prep_kernel(const float* __restrict__ A, const float* __restrict__ P,
                            float* __restrict__ out) {
    int row  = blockIdx.x * 8 + (threadIdx.x >> 5);
    int lane = threadIdx.x & 31;
    float a0 = A[(size_t)row * DIM + lane], a1 = A[(size_t)row * DIM + lane + 32];
    float p0 = P[(size_t)row * DIM + lane], p1 = P[(size_t)row * DIM + lane + 32];
    float sa = a0 * a0 + a1 * a1;
    float sp = p0 * p0 + p1 * p1;
    float d  = a0 * p0 + a1 * p1;
    #pragma unroll
    for (int o = 16; o; o >>= 1) {
        sa += __shfl_xor_sync(0xffffffffu, sa, o);
        sp += __shfl_xor_sync(0xffffffffu, sp, o);
        d  += __shfl_xor_sync(0xffffffffu, d,  o);
    }
    float ra = rsqrtf(fmaxf(sa, 1e-24f));
    float rp = rsqrtf(fmaxf(sp, 1e-24f));
    float va0 = a0 * ra, va1 = a1 * ra;
    float vp0 = p0 * rp, vp1 = p1 * rp;
    size_t ia = (size_t)row * DIM, ip = (size_t)(row + NROWS) * DIM;
    g_Xn[ia + lane]      = __float2bfloat16(va0);
    g_Xn[ia + lane + 32] = __float2bfloat16(va1);
    g_Xn[ip + lane]      = __float2bfloat16(vp0);
    g_Xn[ip + lane + 32] = __float2bfloat16(vp1);
    g_Xs[ia + lane]      = __float2bfloat16(va0 * SCALE_L2E);
    g_Xs[ia + lane + 32] = __float2bfloat16(va1 * SCALE_L2E);
    g_Xs[ip + lane]      = __float2bfloat16(vp0 * SCALE_L2E);
    g_Xs[ip + lane + 32] = __float2bfloat16(vp1 * SCALE_L2E);
    if (lane == 0) {
        g_pos[row] = 20.0f * d / fmaxf(sqrtf(sa) * sqrtf(sp), 1e-6f);
        g_part[row] = 0.0f;
        g_part[row + NROWS] = 0.0f;
    }
    if (blockIdx.x == 0 && threadIdx.x == 0) out[0] = 0.0f;
}

// ---------------- kernel 2: persistent column-major triangle GEMM ----------------
// CTA owns a contiguous range of column-major triangle tiles. Rs (column operand,
// unscaled) loads once per column; Ls (row operand, scaled) double-buffered via
// cp.async. Col partials accumulate in registers ACROSS the column, flushed once
// per column change via smem staging. Row sums flushed per tile (4 shfl + 2
// atomics). Diagonal tiles keep strict upper only (replaces -2*e^{1/T} exactly).
__global__ void __launch_bounds__(256, 2) mma_kernel(int Q, int R) {
    extern __shared__ __align__(16) unsigned char smem[];
    uint32_t sbase = smem_u32(smem);
    uint32_t RsBase = sbase + RSOFF;
    float* colpart = (float*)(smem + CPOFF);

    int c = blockIdx.x;
    int t0 = c * Q + min(c, R);
    int t1 = t0 + Q + (c < R ? 1 : 0);
    if (t0 >= t1) return;

    int tid = threadIdx.x, wid = tid >> 5, lane = tid & 31;
    int gid = lane >> 2, tig = lane & 3;
    int b_u = (lane >> 4) & 1;
    int b_h = (lane >> 3) & 1;
    int b_r = lane & 7;

    float cs[16][2];
    #pragma unroll
    for (int i = 0; i < 16; ++i) { cs[i][0] = 0.0f; cs[i][1] = 0.0f; }

    int cur_bj = -1;
    int buf = 0;

    for (int t = t0; t < t1; ++t) {
        int bj = col_of(t);
        int bi = t - bj * (bj + 1) / 2;

        if (bj != cur_bj) {
            // ---- flush accumulated col partials of the previous column ----
            if (cur_bj >= 0) {
                __syncthreads();                 // all warps done with mainloop & colpart
                int slice = wid * 8 + gid;       // 0..63
                #pragma unroll
                for (int ci = 0; ci < 16; ++ci)
                    *(float2*)&colpart[slice * CPAD + ci * 8 + tig * 2] =
                        make_float2(cs[ci][0], cs[ci][1]);
                __syncthreads();
                int col = tid & 127, h = tid >> 7;
                float s = 0.0f;
                #pragma unroll
                for (int k = 0; k < 32; ++k) s += colpart[(h * 32 + k) * CPAD + col];
                atomicAdd(&g_part[cur_bj * BT + col], s);
                #pragma unroll
                for (int i = 0; i < 16; ++i) { cs[i][0] = 0.0f; cs[i][1] = 0.0f; }
            }
            __syncthreads();                     // old Rs readers done; colpart reduce done
            // ---- load Rs(bj) and first Ls(bi) of this column ----
            const uint4* Rg = (const uint4*)(g_Xn + (size_t)bj * BT * DIM);
            const uint4* Lg = (const uint4*)(g_Xs + (size_t)bi * BT * DIM);
            uint32_t lb = sbase + (uint32_t)buf * TILEB;
            #pragma unroll
            for (int it = 0; it < 4; ++it) {
                int f = tid + it * 256;
                uint32_t off = (uint32_t)(f >> 3) * ROWB + (uint32_t)(f & 7) * 16;
                cp16(RsBase + off, Rg + f);
                cp16(lb + off, Lg + f);
            }
            asm volatile("cp.async.commit_group;" ::: "memory");
            asm volatile("cp.async.wait_group 0;" ::: "memory");
            __syncthreads();
            cur_bj = bj;
        } else {
            // Ls(bi) was prefetched into buf by the previous iteration
            asm volatile("cp.async.wait_group 0;" ::: "memory");
            __syncthreads();
        }

        // ---- prefetch next Ls if the next tile stays in this column ----
        bool pref = (t + 1 < t1) && (bi + 1 <= bj);
        if (pref) {
            const uint4* Lg = (const uint4*)(g_Xs + (size_t)(bi + 1) * BT * DIM);
            uint32_t nb = sbase + (uint32_t)(buf ^ 1) * TILEB;
            #pragma unroll
            for (int it = 0; it < 4; ++it) {
                int f = tid + it * 256;
                uint32_t off = (uint32_t)(f >> 3) * ROWB + (uint32_t)(f & 7) * 16;
                cp16(nb + off, Lg + f);
            }
            asm volatile("cp.async.commit_group;" ::: "memory");
        }

        uint32_t Lbase = sbase + (uint32_t)buf * TILEB;
        bool diag = (bi == bj);
        int grow0 = bi * BT, gcol0 = bj * BT;

        // A fragments for this warp's 16-row strip (all of K=64)
        uint32_t a[4][4];
        {
            int r  = wid * 16 + (lane & 15);
            int kh = (lane >> 4) * 8;
            #pragma unroll
            for (int kc = 0; kc < 4; ++kc) {
                uint32_t addr = Lbase + (uint32_t)r * ROWB + (uint32_t)(kc * 16 + kh) * 2;
                asm volatile("ldmatrix.sync.aligned.m8n8.x4.shared.b16 {%0,%1,%2,%3}, [%4];"
                             : "=r"(a[kc][0]), "=r"(a[kc][1]), "=r"(a[kc][2]), "=r"(a[kc][3])
                             : "r"(addr));
            }
        }

        int myrow0 = grow0 + wid * 16 + gid;
        int myrow1 = myrow0 + 8;
        float row0s = 0.0f, row1s = 0.0f;

        #pragma unroll
        for (int n2 = 0; n2 < 8; ++n2) {
            uint32_t b[2][4][2];
            #pragma unroll
            for (int kc = 0; kc < 4; ++kc) {
                uint32_t addr = RsBase + (uint32_t)(n2 * 16 + b_u * 8 + b_r) * ROWB
                              + (uint32_t)(kc * 16 + b_h * 8) * 2;
                asm volatile("ldmatrix.sync.aligned.m8n8.x4.shared.b16 {%0,%1,%2,%3}, [%4];"
                             : "=r"(b[0][kc][0]), "=r"(b[0][kc][1]),
                               "=r"(b[1][kc][0]), "=r"(b[1][kc][1])
                             : "r"(addr));
            }
            float c4[2][4] = {};
            #pragma unroll
            for (int kc = 0; kc < 4; ++kc) {
                #pragma unroll
                for (int u = 0; u < 2; ++u) {
                    asm volatile(
                        "mma.sync.aligned.m16n8k16.row.col.f32.bf16.bf16.f32 "
                        "{%0,%1,%2,%3}, {%4,%5,%6,%7}, {%8,%9}, {%0,%1,%2,%3};"
                        : "+f"(c4[u][0]), "+f"(c4[u][1]), "+f"(c4[u][2]), "+f"(c4[u][3])
                        : "r"(a[kc][0]), "r"(a[kc][1]), "r"(a[kc][2]), "r"(a[kc][3]),
                          "r"(b[u][kc][0]), "r"(b[u][kc][1]));
                }
            }
            #pragma unroll
            for (int u = 0; u < 2; ++u) {
                float e0 = ex2f(c4[u][0]), e1 = ex2f(c4[u][1]);
                float e2 = ex2f(c4[u][2]), e3 = ex2f(c4[u][3]);
                if (diag) {   // strict upper triangle only
                    int gc0 = gcol0 + (n2 * 2 + u) * 8 + tig * 2;
                    if (gc0     <= myrow0) e0 = 0.0f;
                    if (gc0 + 1 <= myrow0) e1 = 0.0f;
                    if (gc0     <= myrow1) e2 = 0.0f;
                    if (gc0 + 1 <= myrow1) e3 = 0.0f;
                }
                row0s += e0 + e1;
                row1s += e2 + e3;
                int ci = n2 * 2 + u;
                cs[ci][0] += e0 + e2;
                cs[ci][1] += e1 + e3;
            }
        }

        // row flush: 4 shfl + 2 spread atomics
        #pragma unroll
        for (int o = 1; o < 4; o <<= 1) {
            row0s += __shfl_xor_sync(0xffffffffu, row0s, o);
            row1s += __shfl_xor_sync(0xffffffffu, row1s, o);
        }
        if (tig == 0) {
            atomicAdd(&g_part[myrow0], row0s);
            atomicAdd(&g_part[myrow1], row1s);
        }

        if (pref) buf ^= 1;
    }

    // ---- final col flush for the last column ----
    __syncthreads();
    {
        int slice = wid * 8 + gid;
        #pragma unroll
        for (int ci = 0; ci < 16; ++ci)
            *(float2*)&colpart[slice * CPAD + ci * 8 + tig * 2] =
                make_float2(cs[ci][0], cs[ci][1]);
    }
    __syncthreads();
    {
        int col = tid & 127, h = tid >> 7;
        float s = 0.0f;
        #pragma unroll
        for (int k = 0; k < 32; ++k) s += colpart[(h * 32 + k) * CPAD + col];
        atomicAdd(&g_part[cur_bj * BT + col], s);
    }
}

// ---------------- kernel 3: loss reduction straight into d_out ----------------
__global__ void loss_kernel(float* __restrict__ out) {
    __shared__ float wsum[8];
    int i = blockIdx.x * 256 + threadIdx.x;
    float s = __logf(g_part[i] + g_part[i + NROWS]) - g_pos[i];
    #pragma unroll
    for (int o = 16; o; o >>= 1) s += __shfl_xor_sync(0xffffffffu, s, o);
    int wid = threadIdx.x >> 5, lane = threadIdx.x & 31;
    if (lane == 0) wsum[wid] = s;
    __syncthreads();
    if (wid == 0) {
        float v = (lane < 8) ? wsum[lane] : 0.0f;
        #pragma unroll
        for (int o = 4; o; o >>= 1) v += __shfl_xor_sync(0xffffffffu, v, o);
        if (lane == 0) atomicAdd(out, v * (1.0f / (float)NROWS));
    }
}

// ---------------- launch ----------------
extern "C" void kernel_launch(void* const* d_in, const int* in_sizes, int n_in,
                              void* d_out, int out_size) {
    const float* A = (const float*)d_in[0];
    const float* P = (const float*)d_in[1];
    int dev = 0, nsm = 148;
    cudaGetDevice(&dev);
    cudaDeviceGetAttribute(&nsm, cudaDevAttrMultiProcessorCount, dev);
    int G = nsm * 2;
    int Q = NTRI / G, R = NTRI % G;
    cudaFuncSetAttribute(mma_kernel, cudaFuncAttributeMaxDynamicSharedMemorySize, SMEM_TOTAL);
    prep_kernel<<<NROWS / 8, 256>>>(A, P, (float*)d_out);
    mma_kernel<<<G, 256, SMEM_TOTAL>>>(Q, R);
    loss_kernel<<<NROWS / 256, 256>>>((float*)d_out);
}

// round 13
// speedup vs baseline: 3.3220x; 1.0080x over previous
#include <cuda_runtime.h>
#include <cuda_bf16.h>
#include <cstdint>
#include <cmath>

#define NROWS 8192
#define XROWS 16384
#define DIM   64
#define BT    128                 // tile dim
#define NT    (XROWS / BT)        // 128 tiles per side
#define NTRI  (NT * (NT + 1) / 2) // 8256 upper-triangle tiles (column-major order)
#define LPAD  72                  // padded smem row stride (bf16 elems)
#define ROWB  (LPAD * 2)          // 144 bytes per smem row
#define TILEB (BT * ROWB)         // 18432 bytes per operand tile
#define CPOFF (4 * TILEB)         // colpart offset: 73728 (2x Ls + 2x Rs buffers)
#define CPAD  132                 // colpart row stride (floats)
#define SMEM_TOTAL (CPOFF + 64 * CPAD * 4)   // 107520 bytes (2 CTAs/SM)

#define SCALE_L2E 28.853900817779268f   // 20 * log2(e)

// ---------------- device scratch ----------------
__device__ __align__(16) __nv_bfloat16 g_Xs[XROWS * DIM];  // normalized * 20*log2(e)
__device__ __align__(16) __nv_bfloat16 g_Xn[XROWS * DIM];  // normalized
__device__ float g_part[XROWS];
__device__ float g_pos[NROWS];
__device__ int   g_done;

static __device__ __forceinline__ uint32_t smem_u32(const void* p) {
    uint32_t a;
    asm("{ .reg .u64 t; cvta.to.shared.u64 t, %1; cvt.u32.u64 %0, t; }" : "=r"(a) : "l"(p));
    return a;
}
static __device__ __forceinline__ float ex2f(float x) {
    float y; asm("ex2.approx.ftz.f32 %0, %1;" : "=f"(y) : "f"(x)); return y;
}
static __device__ __forceinline__ void cp16(uint32_t dst, const void* src) {
    asm volatile("cp.async.cg.shared.global [%0], [%1], 16;" :: "r"(dst), "l"(src) : "memory");
}
// column-major triangle: t = bj*(bj+1)/2 + bi, 0 <= bi <= bj
static __device__ __forceinline__ int col_of(int t) {
    int bj = (int)((sqrtf(8.0f * (float)t + 1.0f) - 1.0f) * 0.5f);
    if (bj < 0) bj = 0;
    if (bj > NT - 1) bj = NT - 1;
    while (bj * (bj + 1) / 2 > t) --bj;
    while ((bj + 1) * (bj + 2) / 2 <= t) ++bj;
    return bj;
}

// ---------------- kernel 1: normalize + bf16 + exact pos logit + zeroing (2 rows/warp) ----------------
__global__ void prep_kernel(const float* __restrict__ A, const float* __restrict__ P,
                            float* __restrict__ out) {
    int r0   = blockIdx.x * 16 + (threadIdx.x >> 5) * 2;   // warp handles rows r0, r0+1
    int lane = threadIdx.x & 31;
    #pragma unroll
    for (int rr = 0; rr < 2; ++rr) {
        int row = r0 + rr;
        float a0 = A[(size_t)row * DIM + lane], a1 = A[(size_t)row * DIM + lane + 32];
        float p0 = P[(size_t)row * DIM + lane], p1 = P[(size_t)row * DIM + lane + 32];
        float sa = a0 * a0 + a1 * a1;
        float sp = p0 * p0 + p1 * p1;
        float d  = a0 * p0 + a1 * p1;
        #pragma unroll
        for (int o = 16; o; o >>= 1) {
            sa += __shfl_xor_sync(0xffffffffu, sa, o);
            sp += __shfl_xor_sync(0xffffffffu, sp, o);
            d  += __shfl_xor_sync(0xffffffffu, d,  o);
        }
        float ra = rsqrtf(fmaxf(sa, 1e-24f));
        float rp = rsqrtf(fmaxf(sp, 1e-24f));
        float va0 = a0 * ra, va1 = a1 * ra;
        float vp0 = p0 * rp, vp1 = p1 * rp;
        size_t ia = (size_t)row * DIM, ip = (size_t)(row + NROWS) * DIM;
        g_Xn[ia + lane]      = __float2bfloat16(va0);
        g_Xn[ia + lane + 32] = __float2bfloat16(va1);
        g_Xn[ip + lane]      = __float2bfloat16(vp0);
        g_Xn[ip + lane + 32] = __float2bfloat16(vp1);
        g_Xs[ia + lane]      = __float2bfloat16(va0 * SCALE_L2E);
        g_Xs[ia + lane + 32] = __float2bfloat16(va1 * SCALE_L2E);
        g_Xs[ip + lane]      = __float2bfloat16(vp0 * SCALE_L2E);
        g_Xs[ip + lane + 32] = __float2bfloat16(vp1 * SCALE_L2E);
        if (lane == 0) {
            g_pos[row] = 20.0f * d / fmaxf(sqrtf(sa) * sqrtf(sp), 1e-6f);
            g_part[row] = 0.0f;
            g_part[row + NROWS] = 0.0f;
        }
    }
    if (blockIdx.x == 0 && threadIdx.x == 0) { out[0] = 0.0f; g_done = 0; }
}

// ---------------- kernel 2: persistent column-major triangle GEMM + fused final loss ----------------
// Contiguous column-major tile range per CTA. Rs AND Ls double-buffered via
// cp.async; next tile (incl. next column's Rs) prefetched during compute.
// Col partials in registers across the column; flushed at column end. The last
// CTA to finish performs the loss reduction into out[0] (threadfence pattern).
__global__ void __launch_bounds__(256, 2) mma_kernel(int Q, int R, int G,
                                                     float* __restrict__ out) {
    extern __shared__ __align__(16) unsigned char smem[];
    uint32_t sbase = smem_u32(smem);        // Ls buffers at 0, TILEB; Rs at 2*TILEB, 3*TILEB
    float* colpart = (float*)(smem + CPOFF);

    int c = blockIdx.x;
    int t0 = c * Q + min(c, R);
    int t1 = t0 + Q + (c < R ? 1 : 0);

    int tid = threadIdx.x, wid = tid >> 5, lane = tid & 31;
    int gid = lane >> 2, tig = lane & 3;
    int b_u = (lane >> 4) & 1;
    int b_h = (lane >> 3) & 1;
    int b_r = lane & 7;

    if (t0 < t1) {
        int bj = col_of(t0);
        int bi = t0 - bj * (bj + 1) / 2;
        int lbuf = 0, rbuf = 0;

        // prefetch first tile (Ls + Rs)
        {
            const uint4* Lg = (const uint4*)(g_Xs + (size_t)bi * BT * DIM);
            const uint4* Rg = (const uint4*)(g_Xn + (size_t)bj * BT * DIM);
            #pragma unroll
            for (int it = 0; it < 4; ++it) {
                int f = tid + it * 256;
                uint32_t off = (uint32_t)(f >> 3) * ROWB + (uint32_t)(f & 7) * 16;
                cp16(sbase + off, Lg + f);
                cp16(sbase + 2 * TILEB + off, Rg + f);
            }
            asm volatile("cp.async.commit_group;" ::: "memory");
        }

        float cs[16][2];
        #pragma unroll
        for (int i = 0; i < 16; ++i) { cs[i][0] = 0.0f; cs[i][1] = 0.0f; }

        for (int t = t0; t < t1; ++t) {
            bool hasn = (t + 1 < t1);
            int bin = bi, bjn = bj;
            bool colchg = false;
            if (hasn) {
                if (bi < bj) { bin = bi + 1; }
                else         { bjn = bj + 1; bin = 0; colchg = true; }
                const uint4* Lg = (const uint4*)(g_Xs + (size_t)bin * BT * DIM);
                uint32_t lb = sbase + (uint32_t)(lbuf ^ 1) * TILEB;
                const uint4* Rg = (const uint4*)(g_Xn + (size_t)bjn * BT * DIM);
                uint32_t rb = sbase + (uint32_t)(2 + (rbuf ^ 1)) * TILEB;
                #pragma unroll
                for (int it = 0; it < 4; ++it) {
                    int f = tid + it * 256;
                    uint32_t off = (uint32_t)(f >> 3) * ROWB + (uint32_t)(f & 7) * 16;
                    cp16(lb + off, Lg + f);
                    if (colchg) cp16(rb + off, Rg + f);
                }
                asm volatile("cp.async.commit_group;" ::: "memory");
                asm volatile("cp.async.wait_group 1;" ::: "memory");
            } else {
                asm volatile("cp.async.wait_group 0;" ::: "memory");
            }
            __syncthreads();   // current buffers ready; also orders colpart reuse

            uint32_t Lbase = sbase + (uint32_t)lbuf * TILEB;
            uint32_t Rbase = sbase + (uint32_t)(2 + rbuf) * TILEB;
            bool diag = (bi == bj);
            int grow0 = bi * BT, gcol0 = bj * BT;

            uint32_t a[4][4];
            {
                int r  = wid * 16 + (lane & 15);
                int kh = (lane >> 4) * 8;
                #pragma unroll
                for (int kc = 0; kc < 4; ++kc) {
                    uint32_t addr = Lbase + (uint32_t)r * ROWB + (uint32_t)(kc * 16 + kh) * 2;
                    asm volatile("ldmatrix.sync.aligned.m8n8.x4.shared.b16 {%0,%1,%2,%3}, [%4];"
                                 : "=r"(a[kc][0]), "=r"(a[kc][1]), "=r"(a[kc][2]), "=r"(a[kc][3])
                                 : "r"(addr));
                }
            }

            int myrow0 = grow0 + wid * 16 + gid;
            int myrow1 = myrow0 + 8;
            float row0s = 0.0f, row1s = 0.0f;

            #pragma unroll
            for (int n2 = 0; n2 < 8; ++n2) {
                uint32_t b[2][4][2];
                #pragma unroll
                for (int kc = 0; kc < 4; ++kc) {
                    uint32_t addr = Rbase + (uint32_t)(n2 * 16 + b_u * 8 + b_r) * ROWB
                                  + (uint32_t)(kc * 16 + b_h * 8) * 2;
                    asm volatile("ldmatrix.sync.aligned.m8n8.x4.shared.b16 {%0,%1,%2,%3}, [%4];"
                                 : "=r"(b[0][kc][0]), "=r"(b[0][kc][1]),
                                   "=r"(b[1][kc][0]), "=r"(b[1][kc][1])
                                 : "r"(addr));
                }
                float c4[2][4] = {};
                #pragma unroll
                for (int kc = 0; kc < 4; ++kc) {
                    #pragma unroll
                    for (int u = 0; u < 2; ++u) {
                        asm volatile(
                            "mma.sync.aligned.m16n8k16.row.col.f32.bf16.bf16.f32 "
                            "{%0,%1,%2,%3}, {%4,%5,%6,%7}, {%8,%9}, {%0,%1,%2,%3};"
                            : "+f"(c4[u][0]), "+f"(c4[u][1]), "+f"(c4[u][2]), "+f"(c4[u][3])
                            : "r"(a[kc][0]), "r"(a[kc][1]), "r"(a[kc][2]), "r"(a[kc][3]),
                              "r"(b[u][kc][0]), "r"(b[u][kc][1]));
                    }
                }
                #pragma unroll
                for (int u = 0; u < 2; ++u) {
                    float e0 = ex2f(c4[u][0]), e1 = ex2f(c4[u][1]);
                    float e2 = ex2f(c4[u][2]), e3 = ex2f(c4[u][3]);
                    if (diag) {   // strict upper triangle only (replaces -2*e^{1/T})
                        int gc0 = gcol0 + (n2 * 2 + u) * 8 + tig * 2;
                        if (gc0     <= myrow0) e0 = 0.0f;
                        if (gc0 + 1 <= myrow0) e1 = 0.0f;
                        if (gc0     <= myrow1) e2 = 0.0f;
                        if (gc0 + 1 <= myrow1) e3 = 0.0f;
                    }
                    row0s += e0 + e1;
                    row1s += e2 + e3;
                    int ci = n2 * 2 + u;
                    cs[ci][0] += e0 + e2;
                    cs[ci][1] += e1 + e3;
                }
            }

            // row flush: 4 shfl + 2 spread atomics
            #pragma unroll
            for (int o = 1; o < 4; o <<= 1) {
                row0s += __shfl_xor_sync(0xffffffffu, row0s, o);
                row1s += __shfl_xor_sync(0xffffffffu, row1s, o);
            }
            if (tig == 0) {
                atomicAdd(&g_part[myrow0], row0s);
                atomicAdd(&g_part[myrow1], row1s);
            }

            // col flush at end of column (or end of range)
            if (!hasn || colchg) {
                __syncthreads();
                int slice = wid * 8 + gid;
                #pragma unroll
                for (int ci = 0; ci < 16; ++ci)
                    *(float2*)&colpart[slice * CPAD + ci * 8 + tig * 2] =
                        make_float2(cs[ci][0], cs[ci][1]);
                __syncthreads();
                int col = tid & 127, h = tid >> 7;
                float s = 0.0f;
                #pragma unroll
                for (int k = 0; k < 32; ++k) s += colpart[(h * 32 + k) * CPAD + col];
                atomicAdd(&g_part[bj * BT + col], s);
                #pragma unroll
                for (int i = 0; i < 16; ++i) { cs[i][0] = 0.0f; cs[i][1] = 0.0f; }
            }

            if (hasn) {
                lbuf ^= 1;
                if (colchg) rbuf ^= 1;
                bi = bin; bj = bjn;
            }
        }
    }

    // ---- fused loss: last CTA reduces g_part -> out[0] ----
    __shared__ int slast;
    __shared__ float wsum[8];
    __threadfence();
    if (tid == 0) slast = (atomicAdd(&g_done, 1) == G - 1) ? 1 : 0;
    __syncthreads();
    if (slast) {
        __threadfence();
        float s = 0.0f;
        for (int i = tid; i < NROWS; i += 256)
            s += __logf(g_part[i] + g_part[i + NROWS]) - g_pos[i];
        #pragma unroll
        for (int o = 16; o; o >>= 1) s += __shfl_xor_sync(0xffffffffu, s, o);
        if (lane == 0) wsum[wid] = s;
        __syncthreads();
        if (wid == 0) {
            float v = (lane < 8) ? wsum[lane] : 0.0f;
            #pragma unroll
            for (int o = 4; o; o >>= 1) v += __shfl_xor_sync(0xffffffffu, v, o);
            if (lane == 0) out[0] = v * (1.0f / (float)NROWS);
        }
    }
}

// ---------------- launch ----------------
extern "C" void kernel_launch(void* const* d_in, const int* in_sizes, int n_in,
                              void* d_out, int out_size) {
    const float* A = (const float*)d_in[0];
    const float* P = (const float*)d_in[1];
    int dev = 0, nsm = 148;
    cudaGetDevice(&dev);
    cudaDeviceGetAttribute(&nsm, cudaDevAttrMultiProcessorCount, dev);
    int G = nsm * 2;
    int Q = NTRI / G, R = NTRI % G;
    cudaFuncSetAttribute(mma_kernel, cudaFuncAttributeMaxDynamicSharedMemorySize, SMEM_TOTAL);
    prep_kernel<<<NROWS / 16, 256>>>(A, P, (float*)d_out);
    mma_kernel<<<G, 256, SMEM_TOTAL>>>(Q, R, G, (float*)d_out);
}